// round 4
// baseline (speedup 1.0000x reference)
#include <cuda_runtime.h>

// GCN collapse: F_in=1 and F_out=1 make both graph convolutions scalar
// propagations. Pipeline:
//   1) deg count over dst (seeded 1 for self loop) -> dinv = rsqrt(deg)
//   2) s[i] = x[i]*dinv[i]; acc1 seeded with s[i] (self loop)
//   3) edge pass: acc1[dst] += s[src]
//   4) agg1 = dinv*acc1; z = sum_f relu(agg1*W1[f]+b1[f])*W2[f]; t = z*dinv;
//      acc2 seeded with t[i]
//   5) edge pass: acc2[dst] += t[src]
//   6) out[i] = dinv*acc2 + b2
//
// edge_index arrives as int32 (harness downcast), shape [2, E] row-major.
// Edge kernels are persistent grid-stride: loop iterations pipeline index
// loads + gathers of iter k+1 against the fire-and-forget REDs of iter k,
// maximizing outstanding L2 sector ops (the measured binder: L2=81%).

#define MAXN 200000
#define EDGE_BLOCKS 1184   // ~8 CTAs per SM on 148-SM GB300
#define TB 256

__device__ int   g_deg[MAXN];
__device__ float g_dinv[MAXN];
__device__ float g_s[MAXN];
__device__ float g_acc1[MAXN];
__device__ float g_t[MAXN];
__device__ float g_acc2[MAXN];

// ------------------------------------------------ init deg with self loop
__global__ void k_init_deg(int n) {
    int i = blockIdx.x * blockDim.x + threadIdx.x;
    if (i < n) g_deg[i] = 1;
}

// ------------------------------------------------------- degree count pass
// persistent grid-stride, 8 edges per thread-iteration via two int4 loads.
__global__ void k_deg(const int* __restrict__ dst, int e) {
    const int stride = gridDim.x * blockDim.x;       // in groups of 8
    const int ngroups = e >> 3;                      // e % 8 handled below
    for (int g = blockIdx.x * blockDim.x + threadIdx.x; g < ngroups; g += stride) {
        const int base = g * 8;
        int4 a = reinterpret_cast<const int4*>(dst + base)[0];
        int4 b = reinterpret_cast<const int4*>(dst + base)[1];
        atomicAdd(&g_deg[a.x], 1);
        atomicAdd(&g_deg[a.y], 1);
        atomicAdd(&g_deg[a.z], 1);
        atomicAdd(&g_deg[a.w], 1);
        atomicAdd(&g_deg[b.x], 1);
        atomicAdd(&g_deg[b.y], 1);
        atomicAdd(&g_deg[b.z], 1);
        atomicAdd(&g_deg[b.w], 1);
    }
    // tail (e not multiple of 8)
    int t0 = ngroups * 8 + (blockIdx.x * blockDim.x + threadIdx.x);
    if (t0 < e) atomicAdd(&g_deg[dst[t0]], 1);
}

// ------------------------------------------- node pass 1: dinv, s, seed acc1
__global__ void k_node1(const float* __restrict__ x, int n) {
    int i = blockIdx.x * blockDim.x + threadIdx.x;
    if (i < n) {
        float dinv = rsqrtf((float)g_deg[i]);        // deg already includes +1
        g_dinv[i] = dinv;
        float sv = x[i] * dinv;
        g_s[i] = sv;
        g_acc1[i] = sv;    // self-loop contribution; dinv[dst] applied later
    }
}

// --------------------------------------- scalar scatter-add over edges
// PASS=0: acc1[dst] += s[src] ; PASS=1: acc2[dst] += t[src]
template <int PASS>
__global__ void k_edge(const int* __restrict__ src,
                       const int* __restrict__ dst, int e) {
    const float* __restrict__ val = (PASS == 0) ? g_s : g_t;
    float* __restrict__ acc = (PASS == 0) ? g_acc1 : g_acc2;
    const int stride = gridDim.x * blockDim.x;       // in groups of 8
    const int ngroups = e >> 3;
    for (int g = blockIdx.x * blockDim.x + threadIdx.x; g < ngroups; g += stride) {
        const int base = g * 8;
        int4 sa = reinterpret_cast<const int4*>(src + base)[0];
        int4 sb = reinterpret_cast<const int4*>(src + base)[1];
        int4 da = reinterpret_cast<const int4*>(dst + base)[0];
        int4 db = reinterpret_cast<const int4*>(dst + base)[1];
        float v0 = __ldg(&val[sa.x]);
        float v1 = __ldg(&val[sa.y]);
        float v2 = __ldg(&val[sa.z]);
        float v3 = __ldg(&val[sa.w]);
        float v4 = __ldg(&val[sb.x]);
        float v5 = __ldg(&val[sb.y]);
        float v6 = __ldg(&val[sb.z]);
        float v7 = __ldg(&val[sb.w]);
        atomicAdd(&acc[da.x], v0);
        atomicAdd(&acc[da.y], v1);
        atomicAdd(&acc[da.z], v2);
        atomicAdd(&acc[da.w], v3);
        atomicAdd(&acc[db.x], v4);
        atomicAdd(&acc[db.y], v5);
        atomicAdd(&acc[db.z], v6);
        atomicAdd(&acc[db.w], v7);
    }
    // tail (e not multiple of 8)
    int t0 = ngroups * 8 + (blockIdx.x * blockDim.x + threadIdx.x);
    if (t0 < e) atomicAdd(&acc[dst[t0]], __ldg(&val[src[t0]]));
}

// ----------------------- node pass 2: layer1 epilogue + layer2 scalar, seed acc2
__global__ void k_node2(const float* __restrict__ W1, const float* __restrict__ b1,
                        const float* __restrict__ W2, int n) {
    int i = blockIdx.x * blockDim.x + threadIdx.x;
    if (i < n) {
        float dinv = g_dinv[i];
        float agg = dinv * g_acc1[i];
        float z = 0.0f;
#pragma unroll
        for (int f = 0; f < 16; f++) {
            float h = fmaf(agg, __ldg(&W1[f]), __ldg(&b1[f]));
            h = fmaxf(h, 0.0f);
            z = fmaf(h, __ldg(&W2[f]), z);
        }
        float tv = z * dinv;
        g_t[i] = tv;
        g_acc2[i] = tv;   // self loop
    }
}

// ----------------------------------------------------------- output pass
__global__ void k_out(float* __restrict__ out, const float* __restrict__ b2, int n) {
    int i = blockIdx.x * blockDim.x + threadIdx.x;
    if (i < n) {
        out[i] = fmaf(g_dinv[i], g_acc2[i], __ldg(&b2[0]));
    }
}

extern "C" void kernel_launch(void* const* d_in, const int* in_sizes, int n_in,
                              void* d_out, int out_size) {
    const float* x   = (const float*)d_in[0];
    const int*   ei  = (const int*)d_in[1];     // [2, E] int32
    const float* W1  = (const float*)d_in[2];
    const float* b1  = (const float*)d_in[3];
    const float* W2  = (const float*)d_in[4];
    const float* b2  = (const float*)d_in[5];
    float*       out = (float*)d_out;

    const int n = in_sizes[0];           // 200000
    const int e = in_sizes[1] / 2;       // 12800000
    const int* src = ei;
    const int* dst = ei + e;

    const int nblk = (n + TB - 1) / TB;
    // persistent grid for edge kernels; cap at work size
    int groups = (e + 7) / 8;
    int eblk = (groups + TB - 1) / TB;
    if (eblk > EDGE_BLOCKS) eblk = EDGE_BLOCKS;

    k_init_deg<<<nblk, TB>>>(n);
    k_deg<<<eblk, TB>>>(dst, e);
    k_node1<<<nblk, TB>>>(x, n);
    k_edge<0><<<eblk, TB>>>(src, dst, e);
    k_node2<<<nblk, TB>>>(W1, b1, W2, n);
    k_edge<1><<<eblk, TB>>>(src, dst, e);
    k_out<<<nblk, TB>>>(out, b2, n);
}

// round 6
// speedup vs baseline: 1.0621x; 1.0621x over previous
#include <cuda_runtime.h>

// GCN collapse: F_in=1 and F_out=1 make both graph convolutions scalar
// propagations. Pipeline:
//   1) deg count over dst (seeded 1 for self loop) -> dinv = rsqrt(deg)
//   2) s[i] = x[i]*dinv[i]; acc1 seeded with s[i] (self loop)
//   3) edge pass: acc1[dst] += s[src]
//   4) agg1 = dinv*acc1; z = sum_f relu(agg1*W1[f]+b1[f])*W2[f]; t = z*dinv;
//      acc2 seeded with t[i]
//   5) edge pass: acc2[dst] += t[src]
//   6) out[i] = dinv*acc2 + b2
//
// edge_index is int32, shape [2, E]. Edge kernels: one-shot full grid
// (R3-proven best), 16 edges/thread in k_edge for max per-warp MLP against
// the LTS data-path roofline (measured binder: L2=81% in R3).

#define MAXN 200000
#define TB 256

__device__ int   g_deg[MAXN];
__device__ float g_dinv[MAXN];
__device__ float g_s[MAXN];
__device__ float g_acc1[MAXN];
__device__ float g_t[MAXN];
__device__ float g_acc2[MAXN];

__device__ __forceinline__ int4 ldcs_int4(const int* p) {
    return __ldcs(reinterpret_cast<const int4*>(p));
}

// ------------------------------------------------ init deg with self loop
__global__ void k_init_deg(int n) {
    int i = blockIdx.x * blockDim.x + threadIdx.x;
    if (i < n) g_deg[i] = 1;
}

// ------------------------------------------------------- degree count pass
// one-shot, 8 edges per thread via two int4 loads (control: unchanged from R3).
__global__ void k_deg(const int* __restrict__ dst, int e) {
    int t = blockIdx.x * blockDim.x + threadIdx.x;
    int base = t * 8;
    if (base + 7 < e) {
        int4 a = ldcs_int4(dst + base);
        int4 b = ldcs_int4(dst + base + 4);
        atomicAdd(&g_deg[a.x], 1);
        atomicAdd(&g_deg[a.y], 1);
        atomicAdd(&g_deg[a.z], 1);
        atomicAdd(&g_deg[a.w], 1);
        atomicAdd(&g_deg[b.x], 1);
        atomicAdd(&g_deg[b.y], 1);
        atomicAdd(&g_deg[b.z], 1);
        atomicAdd(&g_deg[b.w], 1);
    } else {
        for (int k = base; k < e; k++) atomicAdd(&g_deg[dst[k]], 1);
    }
}

// ------------------------------------------- node pass 1: dinv, s, seed acc1
__global__ void k_node1(const float* __restrict__ x, int n) {
    int i = blockIdx.x * blockDim.x + threadIdx.x;
    if (i < n) {
        float dinv = rsqrtf((float)g_deg[i]);        // deg already includes +1
        g_dinv[i] = dinv;
        float sv = x[i] * dinv;
        g_s[i] = sv;
        g_acc1[i] = sv;    // self-loop contribution; dinv[dst] applied later
    }
}

// --------------------------------------- scalar scatter-add over edges
// 16 edges per thread: all index loads first, then 16 independent gathers,
// then 16 fire-and-forget REDs. PASS=0: acc1 += s[src]; PASS=1: acc2 += t[src].
template <int PASS>
__global__ void k_edge(const int* __restrict__ src,
                       const int* __restrict__ dst, int e) {
    const float* __restrict__ val = (PASS == 0) ? g_s : g_t;
    float* __restrict__ acc = (PASS == 0) ? g_acc1 : g_acc2;
    int t = blockIdx.x * blockDim.x + threadIdx.x;
    int base = t * 16;
    if (base + 15 < e) {
        int4 s0 = ldcs_int4(src + base);
        int4 s1 = ldcs_int4(src + base + 4);
        int4 s2 = ldcs_int4(src + base + 8);
        int4 s3 = ldcs_int4(src + base + 12);
        int4 d0 = ldcs_int4(dst + base);
        int4 d1 = ldcs_int4(dst + base + 4);
        int4 d2 = ldcs_int4(dst + base + 8);
        int4 d3 = ldcs_int4(dst + base + 12);
        float v0  = __ldg(&val[s0.x]);
        float v1  = __ldg(&val[s0.y]);
        float v2  = __ldg(&val[s0.z]);
        float v3  = __ldg(&val[s0.w]);
        float v4  = __ldg(&val[s1.x]);
        float v5  = __ldg(&val[s1.y]);
        float v6  = __ldg(&val[s1.z]);
        float v7  = __ldg(&val[s1.w]);
        float v8  = __ldg(&val[s2.x]);
        float v9  = __ldg(&val[s2.y]);
        float v10 = __ldg(&val[s2.z]);
        float v11 = __ldg(&val[s2.w]);
        float v12 = __ldg(&val[s3.x]);
        float v13 = __ldg(&val[s3.y]);
        float v14 = __ldg(&val[s3.z]);
        float v15 = __ldg(&val[s3.w]);
        atomicAdd(&acc[d0.x], v0);
        atomicAdd(&acc[d0.y], v1);
        atomicAdd(&acc[d0.z], v2);
        atomicAdd(&acc[d0.w], v3);
        atomicAdd(&acc[d1.x], v4);
        atomicAdd(&acc[d1.y], v5);
        atomicAdd(&acc[d1.z], v6);
        atomicAdd(&acc[d1.w], v7);
        atomicAdd(&acc[d2.x], v8);
        atomicAdd(&acc[d2.y], v9);
        atomicAdd(&acc[d2.z], v10);
        atomicAdd(&acc[d2.w], v11);
        atomicAdd(&acc[d3.x], v12);
        atomicAdd(&acc[d3.y], v13);
        atomicAdd(&acc[d3.z], v14);
        atomicAdd(&acc[d3.w], v15);
    } else {
        for (int k = base; k < e; k++)
            atomicAdd(&acc[dst[k]], __ldg(&val[src[k]]));
    }
}

// ----------------------- node pass 2: layer1 epilogue + layer2 scalar, seed acc2
__global__ void k_node2(const float* __restrict__ W1, const float* __restrict__ b1,
                        const float* __restrict__ W2, int n) {
    int i = blockIdx.x * blockDim.x + threadIdx.x;
    if (i < n) {
        float dinv = g_dinv[i];
        float agg = dinv * g_acc1[i];
        float z = 0.0f;
#pragma unroll
        for (int f = 0; f < 16; f++) {
            float h = fmaf(agg, __ldg(&W1[f]), __ldg(&b1[f]));
            h = fmaxf(h, 0.0f);
            z = fmaf(h, __ldg(&W2[f]), z);
        }
        float tv = z * dinv;
        g_t[i] = tv;
        g_acc2[i] = tv;   // self loop
    }
}

// ----------------------------------------------------------- output pass
__global__ void k_out(float* __restrict__ out, const float* __restrict__ b2, int n) {
    int i = blockIdx.x * blockDim.x + threadIdx.x;
    if (i < n) {
        out[i] = fmaf(g_dinv[i], g_acc2[i], __ldg(&b2[0]));
    }
}

extern "C" void kernel_launch(void* const* d_in, const int* in_sizes, int n_in,
                              void* d_out, int out_size) {
    const float* x   = (const float*)d_in[0];
    const int*   ei  = (const int*)d_in[1];     // [2, E] int32
    const float* W1  = (const float*)d_in[2];
    const float* b1  = (const float*)d_in[3];
    const float* W2  = (const float*)d_in[4];
    const float* b2  = (const float*)d_in[5];
    float*       out = (float*)d_out;

    const int n = in_sizes[0];           // 200000
    const int e = in_sizes[1] / 2;       // 12800000
    const int* src = ei;
    const int* dst = ei + e;

    const int nblk = (n + TB - 1) / TB;
    const int g8  = (e + 7) / 8;                  // 8 edges/thread (deg)
    const int dblk = (g8 + TB - 1) / TB;
    const int g16 = (e + 15) / 16;                // 16 edges/thread (edge)
    const int eblk = (g16 + TB - 1) / TB;

    k_init_deg<<<nblk, TB>>>(n);
    k_deg<<<dblk, TB>>>(dst, e);
    k_node1<<<nblk, TB>>>(x, n);
    k_edge<0><<<eblk, TB>>>(src, dst, e);
    k_node2<<<nblk, TB>>>(W1, b1, W2, n);
    k_edge<1><<<eblk, TB>>>(src, dst, e);
    k_out<<<nblk, TB>>>(out, b2, n);
}

// round 7
// speedup vs baseline: 1.0819x; 1.0186x over previous
#include <cuda_runtime.h>

// GCN collapse: F_in=1 and F_out=1 make both graph convolutions scalar
// propagations. Pipeline:
//   1) deg count over dst (seeded 1 for self loop) -> dinv = rsqrt(deg)
//   2) s[i] = x[i]*dinv[i]; acc1 seeded with s[i] (self loop)
//   3) edge pass: acc1[dst] += s[src]
//   4) agg1 = dinv*acc1; z = sum_f relu(agg1*W1[f]+b1[f])*W2[f]; t = z*dinv;
//      acc2 seeded with t[i]
//   5) edge pass: acc2[dst] += t[src]
//   6) out[i] = dinv*acc2 + b2
//
// Shape decisions are measurement-driven:
//   - k_edge: one-shot grid, 8 edges/thread, TB=256, plain loads (R3: 106us,
//     occ 87.6%, L2 81% — beat both persistent grids (R4) and 16/thread (R6)).
//   - k_deg: no gather, so latency-exposed; 16 edges/thread + __ldcs streams
//     for extra MLP at low register cost.

#define MAXN 200000
#define TB 256

__device__ int   g_deg[MAXN];
__device__ float g_dinv[MAXN];
__device__ float g_s[MAXN];
__device__ float g_acc1[MAXN];
__device__ float g_t[MAXN];
__device__ float g_acc2[MAXN];

__device__ __forceinline__ int4 ldcs_int4(const int* p) {
    return __ldcs(reinterpret_cast<const int4*>(p));
}

// ------------------------------------------------ init deg with self loop
__global__ void k_init_deg(int n) {
    int i = blockIdx.x * blockDim.x + threadIdx.x;
    if (i < n) g_deg[i] = 1;
}

// ------------------------------------------------------- degree count pass
// one-shot, 16 edges per thread via four streaming int4 loads.
__global__ void k_deg(const int* __restrict__ dst, int e) {
    int t = blockIdx.x * blockDim.x + threadIdx.x;
    int base = t * 16;
    if (base + 15 < e) {
        int4 a = ldcs_int4(dst + base);
        int4 b = ldcs_int4(dst + base + 4);
        int4 c = ldcs_int4(dst + base + 8);
        int4 d = ldcs_int4(dst + base + 12);
        atomicAdd(&g_deg[a.x], 1);
        atomicAdd(&g_deg[a.y], 1);
        atomicAdd(&g_deg[a.z], 1);
        atomicAdd(&g_deg[a.w], 1);
        atomicAdd(&g_deg[b.x], 1);
        atomicAdd(&g_deg[b.y], 1);
        atomicAdd(&g_deg[b.z], 1);
        atomicAdd(&g_deg[b.w], 1);
        atomicAdd(&g_deg[c.x], 1);
        atomicAdd(&g_deg[c.y], 1);
        atomicAdd(&g_deg[c.z], 1);
        atomicAdd(&g_deg[c.w], 1);
        atomicAdd(&g_deg[d.x], 1);
        atomicAdd(&g_deg[d.y], 1);
        atomicAdd(&g_deg[d.z], 1);
        atomicAdd(&g_deg[d.w], 1);
    } else {
        for (int k = base; k < e; k++) atomicAdd(&g_deg[dst[k]], 1);
    }
}

// ------------------------------------------- node pass 1: dinv, s, seed acc1
__global__ void k_node1(const float* __restrict__ x, int n) {
    int i = blockIdx.x * blockDim.x + threadIdx.x;
    if (i < n) {
        float dinv = rsqrtf((float)g_deg[i]);        // deg already includes +1
        g_dinv[i] = dinv;
        float sv = x[i] * dinv;
        g_s[i] = sv;
        g_acc1[i] = sv;    // self-loop contribution; dinv[dst] applied later
    }
}

// --------------------------------------- scalar scatter-add over edges
// R3-proven shape: 8 edges per thread, two int4 index loads, 8 independent
// gathers, then 8 fire-and-forget REDs.
// PASS=0: acc1 += s[src]; PASS=1: acc2 += t[src].
template <int PASS>
__global__ void k_edge(const int* __restrict__ src,
                       const int* __restrict__ dst, int e) {
    const float* __restrict__ val = (PASS == 0) ? g_s : g_t;
    float* __restrict__ acc = (PASS == 0) ? g_acc1 : g_acc2;
    int t = blockIdx.x * blockDim.x + threadIdx.x;
    int base = t * 8;
    if (base + 7 < e) {
        int4 sa = reinterpret_cast<const int4*>(src + base)[0];
        int4 sb = reinterpret_cast<const int4*>(src + base)[1];
        int4 da = reinterpret_cast<const int4*>(dst + base)[0];
        int4 db = reinterpret_cast<const int4*>(dst + base)[1];
        float v0 = __ldg(&val[sa.x]);
        float v1 = __ldg(&val[sa.y]);
        float v2 = __ldg(&val[sa.z]);
        float v3 = __ldg(&val[sa.w]);
        float v4 = __ldg(&val[sb.x]);
        float v5 = __ldg(&val[sb.y]);
        float v6 = __ldg(&val[sb.z]);
        float v7 = __ldg(&val[sb.w]);
        atomicAdd(&acc[da.x], v0);
        atomicAdd(&acc[da.y], v1);
        atomicAdd(&acc[da.z], v2);
        atomicAdd(&acc[da.w], v3);
        atomicAdd(&acc[db.x], v4);
        atomicAdd(&acc[db.y], v5);
        atomicAdd(&acc[db.z], v6);
        atomicAdd(&acc[db.w], v7);
    } else {
        for (int k = base; k < e; k++)
            atomicAdd(&acc[dst[k]], __ldg(&val[src[k]]));
    }
}

// ----------------------- node pass 2: layer1 epilogue + layer2 scalar, seed acc2
__global__ void k_node2(const float* __restrict__ W1, const float* __restrict__ b1,
                        const float* __restrict__ W2, int n) {
    int i = blockIdx.x * blockDim.x + threadIdx.x;
    if (i < n) {
        float dinv = g_dinv[i];
        float agg = dinv * g_acc1[i];
        float z = 0.0f;
#pragma unroll
        for (int f = 0; f < 16; f++) {
            float h = fmaf(agg, __ldg(&W1[f]), __ldg(&b1[f]));
            h = fmaxf(h, 0.0f);
            z = fmaf(h, __ldg(&W2[f]), z);
        }
        float tv = z * dinv;
        g_t[i] = tv;
        g_acc2[i] = tv;   // self loop
    }
}

// ----------------------------------------------------------- output pass
__global__ void k_out(float* __restrict__ out, const float* __restrict__ b2, int n) {
    int i = blockIdx.x * blockDim.x + threadIdx.x;
    if (i < n) {
        out[i] = fmaf(g_dinv[i], g_acc2[i], __ldg(&b2[0]));
    }
}

extern "C" void kernel_launch(void* const* d_in, const int* in_sizes, int n_in,
                              void* d_out, int out_size) {
    const float* x   = (const float*)d_in[0];
    const int*   ei  = (const int*)d_in[1];     // [2, E] int32
    const float* W1  = (const float*)d_in[2];
    const float* b1  = (const float*)d_in[3];
    const float* W2  = (const float*)d_in[4];
    const float* b2  = (const float*)d_in[5];
    float*       out = (float*)d_out;

    const int n = in_sizes[0];           // 200000
    const int e = in_sizes[1] / 2;       // 12800000
    const int* src = ei;
    const int* dst = ei + e;

    const int nblk = (n + TB - 1) / TB;
    const int g16 = (e + 15) / 16;                // 16 edges/thread (deg)
    const int dblk = (g16 + TB - 1) / TB;
    const int g8  = (e + 7) / 8;                  // 8 edges/thread (edge)
    const int eblk = (g8 + TB - 1) / TB;

    k_init_deg<<<nblk, TB>>>(n);
    k_deg<<<dblk, TB>>>(dst, e);
    k_node1<<<nblk, TB>>>(x, n);
    k_edge<0><<<eblk, TB>>>(src, dst, e);
    k_node2<<<nblk, TB>>>(W1, b1, W2, n);
    k_edge<1><<<eblk, TB>>>(src, dst, e);
    k_out<<<nblk, TB>>>(out, b2, n);
}

// round 8
// speedup vs baseline: 1.1323x; 1.0467x over previous
#include <cuda_runtime.h>
#include <cuda_fp16.h>

// GCN collapse: F_in=1 and F_out=1 make both graph convolutions scalar
// propagations. Pipeline:
//   1) deg count over dst (seeded 1 for self loop) -> dinv = rsqrt(deg)
//   2) s[i] = half(x[i]*dinv[i]); acc1 seeded with s[i] (self loop)
//   3) edge pass: acc1[dst] += s[src]          (fp16 gather, fp32 atomics)
//   4) agg1 = dinv*acc1; z = sum_f relu(agg1*W1[f]+b1[f])*W2[f]; t = half(z*dinv);
//      acc2 seeded with t[i]
//   5) edge pass: acc2[dst] += t[src]
//   6) out[i] = dinv*acc2 + b2
//
// Measured shape decisions:
//   - edge + deg kernels: one-shot grid, 8 edges/thread, TB=256, plain loads
//     (R3 optimum: beat persistent grids R4, 16/thread R6, ldcs-deg R7).
//   - NEW: s/t stored as __half (400KB vs 800KB) -> random-gather L1 hit
//     ~28% -> ~57%, cutting L2 gather sectors ~40% (the measured binder).
//     Accumulation stays fp32 (exact atomics); only gathered operand is
//     rounded (<=4.9e-4 relative), expected norm rel_err ~2e-4 << 1e-3.

#define MAXN 200000
#define TB 256

__device__ int    g_deg[MAXN];
__device__ float  g_dinv[MAXN];
__device__ __half g_s[MAXN];
__device__ float  g_acc1[MAXN];
__device__ __half g_t[MAXN];
__device__ float  g_acc2[MAXN];

// ------------------------------------------------ init deg with self loop
__global__ void k_init_deg(int n) {
    int i = blockIdx.x * blockDim.x + threadIdx.x;
    if (i < n) g_deg[i] = 1;
}

// ------------------------------------------------------- degree count pass
// one-shot, 8 edges per thread via two int4 loads (R3-proven shape).
__global__ void k_deg(const int* __restrict__ dst, int e) {
    int t = blockIdx.x * blockDim.x + threadIdx.x;
    int base = t * 8;
    if (base + 7 < e) {
        int4 a = reinterpret_cast<const int4*>(dst + base)[0];
        int4 b = reinterpret_cast<const int4*>(dst + base)[1];
        atomicAdd(&g_deg[a.x], 1);
        atomicAdd(&g_deg[a.y], 1);
        atomicAdd(&g_deg[a.z], 1);
        atomicAdd(&g_deg[a.w], 1);
        atomicAdd(&g_deg[b.x], 1);
        atomicAdd(&g_deg[b.y], 1);
        atomicAdd(&g_deg[b.z], 1);
        atomicAdd(&g_deg[b.w], 1);
    } else {
        for (int k = base; k < e; k++) atomicAdd(&g_deg[dst[k]], 1);
    }
}

// ------------------------------------------- node pass 1: dinv, s, seed acc1
__global__ void k_node1(const float* __restrict__ x, int n) {
    int i = blockIdx.x * blockDim.x + threadIdx.x;
    if (i < n) {
        float dinv = rsqrtf((float)g_deg[i]);        // deg already includes +1
        g_dinv[i] = dinv;
        float sv = x[i] * dinv;
        g_s[i] = __float2half_rn(sv);
        g_acc1[i] = sv;    // self loop seeded at full precision
    }
}

// --------------------------------------- scalar scatter-add over edges
// 8 edges/thread: two int4 index loads, 8 independent fp16 gathers,
// then 8 fire-and-forget fp32 REDs.
// PASS=0: acc1 += s[src]; PASS=1: acc2 += t[src].
template <int PASS>
__global__ void k_edge(const int* __restrict__ src,
                       const int* __restrict__ dst, int e) {
    const __half* __restrict__ val = (PASS == 0) ? g_s : g_t;
    float* __restrict__ acc = (PASS == 0) ? g_acc1 : g_acc2;
    int t = blockIdx.x * blockDim.x + threadIdx.x;
    int base = t * 8;
    if (base + 7 < e) {
        int4 sa = reinterpret_cast<const int4*>(src + base)[0];
        int4 sb = reinterpret_cast<const int4*>(src + base)[1];
        int4 da = reinterpret_cast<const int4*>(dst + base)[0];
        int4 db = reinterpret_cast<const int4*>(dst + base)[1];
        float v0 = __half2float(__ldg(&val[sa.x]));
        float v1 = __half2float(__ldg(&val[sa.y]));
        float v2 = __half2float(__ldg(&val[sa.z]));
        float v3 = __half2float(__ldg(&val[sa.w]));
        float v4 = __half2float(__ldg(&val[sb.x]));
        float v5 = __half2float(__ldg(&val[sb.y]));
        float v6 = __half2float(__ldg(&val[sb.z]));
        float v7 = __half2float(__ldg(&val[sb.w]));
        atomicAdd(&acc[da.x], v0);
        atomicAdd(&acc[da.y], v1);
        atomicAdd(&acc[da.z], v2);
        atomicAdd(&acc[da.w], v3);
        atomicAdd(&acc[db.x], v4);
        atomicAdd(&acc[db.y], v5);
        atomicAdd(&acc[db.z], v6);
        atomicAdd(&acc[db.w], v7);
    } else {
        for (int k = base; k < e; k++)
            atomicAdd(&acc[dst[k]], __half2float(__ldg(&val[src[k]])));
    }
}

// ----------------------- node pass 2: layer1 epilogue + layer2 scalar, seed acc2
__global__ void k_node2(const float* __restrict__ W1, const float* __restrict__ b1,
                        const float* __restrict__ W2, int n) {
    int i = blockIdx.x * blockDim.x + threadIdx.x;
    if (i < n) {
        float dinv = g_dinv[i];
        float agg = dinv * g_acc1[i];
        float z = 0.0f;
#pragma unroll
        for (int f = 0; f < 16; f++) {
            float h = fmaf(agg, __ldg(&W1[f]), __ldg(&b1[f]));
            h = fmaxf(h, 0.0f);
            z = fmaf(h, __ldg(&W2[f]), z);
        }
        float tv = z * dinv;
        g_t[i] = __float2half_rn(tv);
        g_acc2[i] = tv;   // self loop seeded at full precision
    }
}

// ----------------------------------------------------------- output pass
__global__ void k_out(float* __restrict__ out, const float* __restrict__ b2, int n) {
    int i = blockIdx.x * blockDim.x + threadIdx.x;
    if (i < n) {
        out[i] = fmaf(g_dinv[i], g_acc2[i], __ldg(&b2[0]));
    }
}

extern "C" void kernel_launch(void* const* d_in, const int* in_sizes, int n_in,
                              void* d_out, int out_size) {
    const float* x   = (const float*)d_in[0];
    const int*   ei  = (const int*)d_in[1];     // [2, E] int32
    const float* W1  = (const float*)d_in[2];
    const float* b1  = (const float*)d_in[3];
    const float* W2  = (const float*)d_in[4];
    const float* b2  = (const float*)d_in[5];
    float*       out = (float*)d_out;

    const int n = in_sizes[0];           // 200000
    const int e = in_sizes[1] / 2;       // 12800000
    const int* src = ei;
    const int* dst = ei + e;

    const int nblk = (n + TB - 1) / TB;
    const int g8  = (e + 7) / 8;                  // 8 edges/thread
    const int eblk = (g8 + TB - 1) / TB;

    k_init_deg<<<nblk, TB>>>(n);
    k_deg<<<eblk, TB>>>(dst, e);
    k_node1<<<nblk, TB>>>(x, n);
    k_edge<0><<<eblk, TB>>>(src, dst, e);
    k_node2<<<nblk, TB>>>(W1, b1, W2, n);
    k_edge<1><<<eblk, TB>>>(src, dst, e);
    k_out<<<nblk, TB>>>(out, b2, n);
}

// round 17
// speedup vs baseline: 1.1432x; 1.0096x over previous
#include <cuda_runtime.h>
#include <cuda_fp16.h>

// GCN collapse to scalar propagation (F_in=1, F_out=1). Pipeline:
//   1) deg count over dst (seeded 1 for self loop) -> dinv = rsqrt(deg)
//   2) s[i] = half(x[i]*dinv[i]); acc1 seeded with x[i]*dinv[i]
//   3) edge pass: acc1[dst] += s[src]   (SMEM-staged gather, fp32 REDs)
//   4) node: agg=dinv*acc1; z=sum_f relu(agg*W1+b1)*W2; t=half(z*dinv); seed acc2
//   5) edge pass: acc2[dst] += t[src]
//   6) out[i] = dinv*acc2 + b2
//
// Measured model (R8): edge pass = 12.8M gather wavefronts (~43us) + 12.8M
// REDG lane-ops (~55us); LSU/L1tex lane-op bound. This round moves the
// random gather into SMEM: persistent kernel (148 CTAs, 1/SM), each stages
// a 100k-node half of the fp16 value array (200KB smem), scans all edges,
// processes only src-in-range (predicated -> no lane-ops when off).
// Divergent LDS costs ~bank-conflict-degree (~4cyc/warp) vs ~32 sector
// wavefronts for divergent LDG: the 43us gather term collapses.

#define MAXN 200000
#define TB 256
#define EB 1024
#define PGRID 148

__device__ int    g_deg[MAXN];
__device__ float  g_dinv[MAXN];
__device__ __half g_s[MAXN];
__device__ float  g_acc1[MAXN];
__device__ __half g_t[MAXN];
__device__ float  g_acc2[MAXN];

// ------------------------------------------------ init deg with self loop
__global__ void k_init_deg(int n) {
    int i = blockIdx.x * blockDim.x + threadIdx.x;
    if (i < n) g_deg[i] = 1;
}

// ------------------------------------------------------- degree count pass
// one-shot, 8 edges per thread via two int4 loads (REDG-floor bound).
__global__ void k_deg(const int* __restrict__ dst, int e) {
    int t = blockIdx.x * blockDim.x + threadIdx.x;
    int base = t * 8;
    if (base + 7 < e) {
        int4 a = reinterpret_cast<const int4*>(dst + base)[0];
        int4 b = reinterpret_cast<const int4*>(dst + base)[1];
        atomicAdd(&g_deg[a.x], 1);
        atomicAdd(&g_deg[a.y], 1);
        atomicAdd(&g_deg[a.z], 1);
        atomicAdd(&g_deg[a.w], 1);
        atomicAdd(&g_deg[b.x], 1);
        atomicAdd(&g_deg[b.y], 1);
        atomicAdd(&g_deg[b.z], 1);
        atomicAdd(&g_deg[b.w], 1);
    } else {
        for (int k = base; k < e; k++) atomicAdd(&g_deg[dst[k]], 1);
    }
}

// ------------------------------------------- node pass 1: dinv, s, seed acc1
__global__ void k_node1(const float* __restrict__ x, int n) {
    int i = blockIdx.x * blockDim.x + threadIdx.x;
    if (i < n) {
        float dinv = rsqrtf((float)g_deg[i]);        // deg already includes +1
        g_dinv[i] = dinv;
        float sv = x[i] * dinv;
        g_s[i] = __float2half_rn(sv);
        g_acc1[i] = sv;    // self loop seeded at full precision
    }
}

// ---------------------------- SMEM-staged scatter-add over a src half-range
// Persistent (1 CTA/SM). Stage val[rbase:rend) into smem, then grid-stride
// over all edges; edges whose src is in range do LDS gather + fp32 RED.
template <int PASS>
__global__ void __launch_bounds__(EB, 1)
k_edge_smem(const int* __restrict__ src, const int* __restrict__ dst,
            int e, int rbase, int rend) {
    const __half* __restrict__ val = (PASS == 0) ? g_s : g_t;
    float* __restrict__ acc = (PASS == 0) ? g_acc1 : g_acc2;
    extern __shared__ __half sh[];

    const int rsize = rend - rbase;
    for (int i = threadIdx.x; i < rsize; i += EB)
        sh[i] = val[rbase + i];
    __syncthreads();

    const int ngroups = e >> 3;          // groups of 8 edges
    const int stride = gridDim.x * EB;
    for (int g = blockIdx.x * EB + threadIdx.x; g < ngroups; g += stride) {
        const int base = g * 8;
        int4 sa = reinterpret_cast<const int4*>(src + base)[0];
        int4 sb = reinterpret_cast<const int4*>(src + base)[1];
        int4 da = reinterpret_cast<const int4*>(dst + base)[0];
        int4 db = reinterpret_cast<const int4*>(dst + base)[1];
        if (sa.x >= rbase && sa.x < rend)
            atomicAdd(&acc[da.x], __half2float(sh[sa.x - rbase]));
        if (sa.y >= rbase && sa.y < rend)
            atomicAdd(&acc[da.y], __half2float(sh[sa.y - rbase]));
        if (sa.z >= rbase && sa.z < rend)
            atomicAdd(&acc[da.z], __half2float(sh[sa.z - rbase]));
        if (sa.w >= rbase && sa.w < rend)
            atomicAdd(&acc[da.w], __half2float(sh[sa.w - rbase]));
        if (sb.x >= rbase && sb.x < rend)
            atomicAdd(&acc[db.x], __half2float(sh[sb.x - rbase]));
        if (sb.y >= rbase && sb.y < rend)
            atomicAdd(&acc[db.y], __half2float(sh[sb.y - rbase]));
        if (sb.z >= rbase && sb.z < rend)
            atomicAdd(&acc[db.z], __half2float(sh[sb.z - rbase]));
        if (sb.w >= rbase && sb.w < rend)
            atomicAdd(&acc[db.w], __half2float(sh[sb.w - rbase]));
    }
    // tail (e not multiple of 8)
    for (int k = ngroups * 8 + blockIdx.x * EB + threadIdx.x; k < e; k += stride) {
        int s0 = src[k];
        if (s0 >= rbase && s0 < rend)
            atomicAdd(&acc[dst[k]], __half2float(sh[s0 - rbase]));
    }
}

// ----------------------- node pass 2: layer1 epilogue + layer2 scalar, seed acc2
__global__ void k_node2(const float* __restrict__ W1, const float* __restrict__ b1,
                        const float* __restrict__ W2, int n) {
    int i = blockIdx.x * blockDim.x + threadIdx.x;
    if (i < n) {
        float dinv = g_dinv[i];
        float agg = dinv * g_acc1[i];
        float z = 0.0f;
#pragma unroll
        for (int f = 0; f < 16; f++) {
            float h = fmaf(agg, __ldg(&W1[f]), __ldg(&b1[f]));
            h = fmaxf(h, 0.0f);
            z = fmaf(h, __ldg(&W2[f]), z);
        }
        float tv = z * dinv;
        g_t[i] = __float2half_rn(tv);
        g_acc2[i] = tv;   // self loop seeded at full precision
    }
}

// ----------------------------------------------------------- output pass
__global__ void k_out(float* __restrict__ out, const float* __restrict__ b2, int n) {
    int i = blockIdx.x * blockDim.x + threadIdx.x;
    if (i < n) {
        out[i] = fmaf(g_dinv[i], g_acc2[i], __ldg(&b2[0]));
    }
}

extern "C" void kernel_launch(void* const* d_in, const int* in_sizes, int n_in,
                              void* d_out, int out_size) {
    const float* x   = (const float*)d_in[0];
    const int*   ei  = (const int*)d_in[1];     // [2, E] int32
    const float* W1  = (const float*)d_in[2];
    const float* b1  = (const float*)d_in[3];
    const float* W2  = (const float*)d_in[4];
    const float* b2  = (const float*)d_in[5];
    float*       out = (float*)d_out;

    const int n = in_sizes[0];           // 200000
    const int e = in_sizes[1] / 2;       // 12800000
    const int* src = ei;
    const int* dst = ei + e;

    const int nblk = (n + TB - 1) / TB;
    const int g8  = (e + 7) / 8;
    const int eblk = (g8 + TB - 1) / TB;

    const int half = (n + 1) / 2;                      // 100000
    const size_t shbytes = (size_t)half * sizeof(__half);  // 200000 B
    cudaFuncSetAttribute(k_edge_smem<0>,
                         cudaFuncAttributeMaxDynamicSharedMemorySize, (int)shbytes);
    cudaFuncSetAttribute(k_edge_smem<1>,
                         cudaFuncAttributeMaxDynamicSharedMemorySize, (int)shbytes);

    k_init_deg<<<nblk, TB>>>(n);
    k_deg<<<eblk, TB>>>(dst, e);
    k_node1<<<nblk, TB>>>(x, n);
    k_edge_smem<0><<<PGRID, EB, shbytes>>>(src, dst, e, 0, half);
    k_edge_smem<0><<<PGRID, EB, shbytes>>>(src, dst, e, half, n);
    k_node2<<<nblk, TB>>>(W1, b1, W2, n);
    k_edge_smem<1><<<PGRID, EB, shbytes>>>(src, dst, e, 0, half);
    k_edge_smem<1><<<PGRID, EB, shbytes>>>(src, dst, e, half, n);
    k_out<<<nblk, TB>>>(out, b2, n);
}